// round 8
// baseline (speedup 1.0000x reference)
#include <cuda_runtime.h>
#include <cuda_fp16.h>
#include <cstdint>

// ---------------- problem constants ----------------
#define M_TOK 2048
#define K_DIM 2048
#define N_DIM 1408
#define N_EXP 8
#define TOP_K 2
#define CAP   1024
#define N_ROWS (M_TOK * TOP_K)
#define W_ELEMS (N_EXP * N_DIM * K_DIM)

// ---------------- scratch ----------------
__device__ int    g_cnt[N_EXP];
__device__ int    g_slot[N_ROWS];
__device__ __half g_x16 [(size_t)N_EXP * CAP * K_DIM];
__device__ __half g_act [(size_t)N_EXP * CAP * N_DIM];
__device__ __half g_stage[(size_t)N_EXP * CAP * K_DIM];
__device__ __half g_gw16[W_ELEMS];
__device__ __half g_uw16[W_ELEMS];
__device__ __half g_dw16[W_ELEMS];

// ---------------- helpers (baseline sm_80 ISA) ----------------
__device__ __forceinline__ uint32_t smem_u32(const void* p) {
    uint32_t a;
    asm("{ .reg .u64 t; cvta.to.shared.u64 t, %1; cvt.u32.u64 %0, t; }" : "=r"(a) : "l"(p));
    return a;
}
__device__ __forceinline__ void cp16(uint32_t s, const void* g) {
    asm volatile("cp.async.cg.shared.global [%0], [%1], 16;" :: "r"(s), "l"(g));
}
#define CP_COMMIT() asm volatile("cp.async.commit_group;" ::: "memory")
#define CP_WAIT2()  asm volatile("cp.async.wait_group 2;" ::: "memory")
#define CP_WAIT1()  asm volatile("cp.async.wait_group 1;" ::: "memory")
#define CP_WAIT0()  asm volatile("cp.async.wait_group 0;" ::: "memory")
__device__ __forceinline__ void ldsm4(uint32_t* r, uint32_t addr) {
    asm volatile("ldmatrix.sync.aligned.m8n8.x4.shared.b16 {%0,%1,%2,%3}, [%4];"
                 : "=r"(r[0]), "=r"(r[1]), "=r"(r[2]), "=r"(r[3]) : "r"(addr));
}
__device__ __forceinline__ void mma16816(float* c, const uint32_t* a, uint32_t b0, uint32_t b1) {
    asm volatile("mma.sync.aligned.m16n8k16.row.col.f32.f16.f16.f32 "
        "{%0,%1,%2,%3},{%4,%5,%6,%7},{%8,%9},{%0,%1,%2,%3};"
        : "+f"(c[0]), "+f"(c[1]), "+f"(c[2]), "+f"(c[3])
        : "r"(a[0]), "r"(a[1]), "r"(a[2]), "r"(a[3]), "r"(b0), "r"(b1));
}
__device__ __forceinline__ uint2 pk4(float4 v) {
    __half2 h0 = __floats2half2_rn(v.x, v.y), h1 = __floats2half2_rn(v.z, v.w);
    return make_uint2(*reinterpret_cast<uint32_t*>(&h0), *reinterpret_cast<uint32_t*>(&h1));
}
__device__ __forceinline__ float swiglu(float g, float u) {
    g = fminf(g, 10.0f);
    u = fminf(fmaxf(u, -10.0f), 10.0f);
    return (g / (1.0f + __expf(-g))) * u;
}
__device__ __forceinline__ uint32_t swz(int row, int c) {
    return (uint32_t)(row * 64 + ((c ^ ((row >> 1) & 3)) << 4));
}

// ---------------- prep kernels ----------------
__global__ void zero_cnt() { if (threadIdx.x < N_EXP) g_cnt[threadIdx.x] = 0; }

// fused route + gather: one block per routed row
__global__ void __launch_bounds__(128) dispatch_kernel(const int* __restrict__ idx,
                                                       const float* __restrict__ H) {
    __shared__ int ss;
    const int r = blockIdx.x;
    if (threadIdx.x == 0) {
        int e = idx[r];
        int p = atomicAdd(&g_cnt[e], 1);
        int s = (p < CAP) ? (e * CAP + p) : -1;
        g_slot[r] = s;
        ss = s;
    }
    __syncthreads();
    const int s = ss;
    if (s < 0) return;
    const float4* src = (const float4*)(H + (size_t)(r >> 1) * K_DIM);
    uint2* dst = (uint2*)(g_x16 + (size_t)s * K_DIM);
#pragma unroll
    for (int i = 0; i < 4; i++) {
        int q = threadIdx.x + i * 128;
        dst[q] = pk4(src[q]);
    }
}

__global__ void __launch_bounds__(256) convw(const float* __restrict__ GW,
                                             const float* __restrict__ UW,
                                             const float* __restrict__ DW) {
    const float* src = (blockIdx.y == 0) ? GW : (blockIdx.y == 1) ? UW : DW;
    __half* dst = (blockIdx.y == 0) ? g_gw16 : (blockIdx.y == 1) ? g_uw16 : g_dw16;
    size_t q = (size_t)blockIdx.x * 256 + threadIdx.x;
    float4 v = ((const float4*)src)[q];
    ((uint2*)dst)[q] = pk4(v);
}

// ---------------- GEMMs ----------------
// stage = 24KB (A 256 rows @0 ..16K, plus 8K of B-material), 4 stages = 96KB
#define STAGE_B 24576
#define NSTAGE  4
extern __shared__ char smc[];

__device__ __forceinline__ void pipe_wait(int kt, int NT) {
    int rem = NT - 1 - kt;
    if (rem >= 2)      CP_WAIT2();
    else if (rem == 1) CP_WAIT1();
    else               CP_WAIT0();
}

// ---------------------------------------------------------------------------
// GEMM1: G = X@GW^T, U = X@UW^T. CTA 256m x 64n (both mats), 512 threads.
// warp (wm 0-3, wn 0-3): 64m x 16n of BOTH G and U. SwiGLU -> g_act.
// stage: A(256 rows)@0, G(64)@16384, U(64)@20480 (rows of 32 fp16 = 64B)
// ---------------------------------------------------------------------------
__global__ void __launch_bounds__(512, 1) gemm1_tc() {
    const int e = blockIdx.z;
    int cnt = g_cnt[e]; if (cnt > CAP) cnt = CAP;
    const int m0 = blockIdx.x * 256;          // m fastest: CTAs share weights in L2
    if (m0 >= cnt) return;
    const int n0 = blockIdx.y * 64;

    const int tid = threadIdx.x, lane = tid & 31, wid = tid >> 5;
    const int wm = wid >> 2, wn = wid & 3;    // 4m x 4n warps
    const int gq = lane >> 2, tg = lane & 3;
    const int lane15 = lane & 15, lhi = lane >> 4;

    const uint32_t su = smem_u32(smc);

    // loaders: lrow 0..127, 3 chunks per thread
    const int lrow = tid >> 2, lc = tid & 3;
    const __half* pa0 = g_x16 + ((size_t)(e * CAP + m0) + lrow) * K_DIM + lc * 8;
    const __half* pa1 = pa0 + (size_t)128 * K_DIM;
    const bool isG = (lrow < 64);
    const int wrow = isG ? lrow : (lrow - 64);
    const __half* pw = (isG ? g_gw16 : g_uw16)
                     + ((size_t)e * N_DIM + n0 + wrow) * K_DIM + lc * 8;
    const uint32_t soA0 = swz(lrow, lc), soA1 = swz(lrow + 128, lc);
    const uint32_t soW  = (isG ? 16384u : 20480u) + swz(wrow, lc);

    auto load = [&](int kt) {
        const uint32_t sb = su + (uint32_t)(kt % NSTAGE) * STAGE_B;
        const int ko = kt * 32;
        cp16(sb + soA0, pa0 + ko);
        cp16(sb + soA1, pa1 + ko);
        cp16(sb + soW,  pw  + ko);
        CP_COMMIT();
    };

    int aoff[4], axr[4];
#pragma unroll
    for (int i = 0; i < 4; i++) {
        int r = wm * 64 + i * 16 + lane15;
        aoff[i] = r * 64; axr[i] = (r >> 1) & 3;
    }
    const int brw = wn * 16 + lane15;
    const int boff = brw * 64, bxr = (brw >> 1) & 3;

    float cG[4][2][4] = {}, cU[4][2][4] = {};

    const int NT = K_DIM / 32;   // 64
    load(0); load(1); load(2);
    for (int kt = 0; kt < NT; ++kt) {
        pipe_wait(kt, NT);
        __syncthreads();
        if (kt + 3 < NT) load(kt + 3);

        const uint32_t sb = su + (uint32_t)(kt % NSTAGE) * STAGE_B;
#pragma unroll
        for (int kh = 0; kh < 2; ++kh) {
            const int ch = 2 * kh + lhi;
            uint32_t bg[4], bu[4];
            ldsm4(bg, sb + 16384 + boff + ((ch ^ bxr) << 4));
            ldsm4(bu, sb + 20480 + boff + ((ch ^ bxr) << 4));
#pragma unroll
            for (int i = 0; i < 4; i++) {
                uint32_t a[4];
                ldsm4(a, sb + aoff[i] + ((ch ^ axr[i]) << 4));
                mma16816(cG[i][0], a, bg[0], bg[2]);
                mma16816(cG[i][1], a, bg[1], bg[3]);
                mma16816(cU[i][0], a, bu[0], bu[2]);
                mma16816(cU[i][1], a, bu[1], bu[3]);
            }
        }
    }

    // SwiGLU epilogue -> fp16 act
#pragma unroll
    for (int i = 0; i < 4; i++) {
        int r0 = wm * 64 + i * 16 + gq;
        int mg0 = m0 + r0, mg1 = mg0 + 8;
        __half* row0 = g_act + ((size_t)e * CAP + mg0) * N_DIM + n0;
        __half* row1 = g_act + ((size_t)e * CAP + mg1) * N_DIM + n0;
#pragma unroll
        for (int j = 0; j < 2; j++) {
            int col = wn * 16 + j * 8 + tg * 2;
            if (mg0 < cnt)
                *(__half2*)(row0 + col) = __floats2half2_rn(
                    swiglu(cG[i][j][0], cU[i][j][0]), swiglu(cG[i][j][1], cU[i][j][1]));
            if (mg1 < cnt)
                *(__half2*)(row1 + col) = __floats2half2_rn(
                    swiglu(cG[i][j][2], cU[i][j][2]), swiglu(cG[i][j][3], cU[i][j][3]));
        }
    }
}

// ---------------------------------------------------------------------------
// GEMM2: D = act@DW^T. CTA 256m x 128n, 512 threads.
// warp (wm 0-3, wn 0-3): 64m x 32n. -> g_stage (fp16, plain stores)
// stage: A(256 rows)@0, B(128 rows)@16384
// ---------------------------------------------------------------------------
__global__ void __launch_bounds__(512, 1) gemm2_tc() {
    const int e = blockIdx.z;
    int cnt = g_cnt[e]; if (cnt > CAP) cnt = CAP;
    const int m0 = blockIdx.x * 256;
    if (m0 >= cnt) return;
    const int n0 = blockIdx.y * 128;

    const int tid = threadIdx.x, lane = tid & 31, wid = tid >> 5;
    const int wm = wid >> 2, wn = wid & 3;
    const int gq = lane >> 2, tg = lane & 3;
    const int lane15 = lane & 15, lhi = lane >> 4;

    const uint32_t su = smem_u32(smc);

    const int lrow = tid >> 2, lc = tid & 3;
    const __half* pa0 = g_act + ((size_t)(e * CAP + m0) + lrow) * N_DIM + lc * 8;
    const __half* pa1 = pa0 + (size_t)128 * N_DIM;
    const __half* pb  = g_dw16 + ((size_t)e * K_DIM + n0 + lrow) * N_DIM + lc * 8;
    const uint32_t soA0 = swz(lrow, lc), soA1 = swz(lrow + 128, lc);
    const uint32_t soB  = 16384u + swz(lrow, lc);

    auto load = [&](int kt) {
        const uint32_t sb = su + (uint32_t)(kt % NSTAGE) * STAGE_B;
        const int ko = kt * 32;
        cp16(sb + soA0, pa0 + ko);
        cp16(sb + soA1, pa1 + ko);
        cp16(sb + soB,  pb  + ko);
        CP_COMMIT();
    };

    int aoff[4], axr[4];
#pragma unroll
    for (int i = 0; i < 4; i++) {
        int r = wm * 64 + i * 16 + lane15;
        aoff[i] = r * 64; axr[i] = (r >> 1) & 3;
    }
    int boff[2], bxr[2];
#pragma unroll
    for (int j = 0; j < 2; j++) {
        int r = wn * 32 + j * 16 + lane15;
        boff[j] = 16384 + r * 64; bxr[j] = (r >> 1) & 3;
    }

    float c[4][4][4] = {};

    const int NT = N_DIM / 32;   // 44
    load(0); load(1); load(2);
    for (int kt = 0; kt < NT; ++kt) {
        pipe_wait(kt, NT);
        __syncthreads();
        if (kt + 3 < NT) load(kt + 3);

        const uint32_t sb = su + (uint32_t)(kt % NSTAGE) * STAGE_B;
#pragma unroll
        for (int kh = 0; kh < 2; ++kh) {
            const int ch = 2 * kh + lhi;
            uint32_t b0[4], b1[4];
            ldsm4(b0, sb + boff[0] + ((ch ^ bxr[0]) << 4));
            ldsm4(b1, sb + boff[1] + ((ch ^ bxr[1]) << 4));
#pragma unroll
            for (int i = 0; i < 4; i++) {
                uint32_t a[4];
                ldsm4(a, sb + aoff[i] + ((ch ^ axr[i]) << 4));
                mma16816(c[i][0], a, b0[0], b0[2]);
                mma16816(c[i][1], a, b0[1], b0[3]);
                mma16816(c[i][2], a, b1[0], b1[2]);
                mma16816(c[i][3], a, b1[1], b1[3]);
            }
        }
    }

    // epilogue: fp16 stores into stage buffer
#pragma unroll
    for (int i = 0; i < 4; i++) {
        int r0 = wm * 64 + i * 16 + gq, r1 = r0 + 8;
        bool v0 = (m0 + r0) < cnt, v1 = (m0 + r1) < cnt;
        __half* o0 = g_stage + ((size_t)e * CAP + m0 + r0) * K_DIM + n0;
        __half* o1 = g_stage + ((size_t)e * CAP + m0 + r1) * K_DIM + n0;
#pragma unroll
        for (int j = 0; j < 4; j++) {
            int col = wn * 32 + j * 8 + tg * 2;
            if (v0) *(__half2*)(o0 + col) = __floats2half2_rn(c[i][j][0], c[i][j][1]);
            if (v1) *(__half2*)(o1 + col) = __floats2half2_rn(c[i][j][2], c[i][j][3]);
        }
    }
}

// combine: out[t] = gate0 * stage[slot0] + gate1 * stage[slot1]
__global__ void __launch_bounds__(256) combine_kernel(const float* __restrict__ gate,
                                                      float* __restrict__ out) {
    int gid = blockIdx.x * 256 + threadIdx.x;
    int t = gid >> 8;
    int c = (gid & 255) * 8;
    int s0 = g_slot[2 * t], s1 = g_slot[2 * t + 1];
    float g0 = gate[2 * t], g1 = gate[2 * t + 1];
    float acc[8] = {0, 0, 0, 0, 0, 0, 0, 0};
    if (s0 >= 0) {
        uint4 v = *(const uint4*)(g_stage + (size_t)s0 * K_DIM + c);
        const __half2* h = (const __half2*)&v;
#pragma unroll
        for (int q = 0; q < 4; q++) {
            float2 f = __half22float2(h[q]);
            acc[2 * q]     = g0 * f.x;
            acc[2 * q + 1] = g0 * f.y;
        }
    }
    if (s1 >= 0) {
        uint4 v = *(const uint4*)(g_stage + (size_t)s1 * K_DIM + c);
        const __half2* h = (const __half2*)&v;
#pragma unroll
        for (int q = 0; q < 4; q++) {
            float2 f = __half22float2(h[q]);
            acc[2 * q]     += g1 * f.x;
            acc[2 * q + 1] += g1 * f.y;
        }
    }
    float4* po = (float4*)(out + (size_t)t * K_DIM + c);
    po[0] = make_float4(acc[0], acc[1], acc[2], acc[3]);
    po[1] = make_float4(acc[4], acc[5], acc[6], acc[7]);
}

// ---------------------------------------------------------------------------
extern "C" void kernel_launch(void* const* d_in, const int* in_sizes, int n_in,
                              void* d_out, int out_size) {
    const float* H   = (const float*)d_in[0];
    const int*   IDX = (const int*)  d_in[1];
    const float* G   = (const float*)d_in[2];
    const float* GW  = (const float*)d_in[3];
    const float* UW  = (const float*)d_in[4];
    const float* DW  = (const float*)d_in[5];
    float* OUT = (float*)d_out;

    const int gsm = NSTAGE * STAGE_B;   // 96KB
    cudaFuncSetAttribute(gemm1_tc, cudaFuncAttributeMaxDynamicSharedMemorySize, gsm);
    cudaFuncSetAttribute(gemm2_tc, cudaFuncAttributeMaxDynamicSharedMemorySize, gsm);

    dim3 cw(W_ELEMS / 4 / 256, 3);
    convw<<<cw, 256>>>(GW, UW, DW);
    zero_cnt<<<1, 32>>>();
    dispatch_kernel<<<N_ROWS, 128>>>(IDX, H);

    dim3 g1(CAP / 256, N_DIM / 64, N_EXP);         // 4 x 22 x 8
    gemm1_tc<<<g1, 512, gsm>>>();
    dim3 g2(CAP / 256, K_DIM / 128, N_EXP);        // 4 x 16 x 8
    gemm2_tc<<<g2, 512, gsm>>>();

    combine_kernel<<<M_TOK * K_DIM / 8 / 256, 256>>>(G, OUT);
}

// round 9
// speedup vs baseline: 1.3097x; 1.3097x over previous
#include <cuda_runtime.h>
#include <cuda_fp16.h>
#include <cstdint>

// ---------------- problem constants ----------------
#define M_TOK 2048
#define K_DIM 2048
#define N_DIM 1408
#define N_EXP 8
#define TOP_K 2
#define CAP   1024
#define N_ROWS (M_TOK * TOP_K)
#define W_ELEMS (N_EXP * N_DIM * K_DIM)

// ---------------- scratch ----------------
__device__ int    g_cnt[N_EXP];
__device__ int    g_slot[N_ROWS];
__device__ __half g_x16 [(size_t)N_EXP * CAP * K_DIM];
__device__ __half g_act [(size_t)N_EXP * CAP * N_DIM];
__device__ __half g_stage[(size_t)N_EXP * CAP * K_DIM];
__device__ __half g_gw16[W_ELEMS];
__device__ __half g_uw16[W_ELEMS];
__device__ __half g_dw16[W_ELEMS];

// ---------------- helpers (baseline sm_80 ISA) ----------------
__device__ __forceinline__ uint32_t smem_u32(const void* p) {
    uint32_t a;
    asm("{ .reg .u64 t; cvta.to.shared.u64 t, %1; cvt.u32.u64 %0, t; }" : "=r"(a) : "l"(p));
    return a;
}
__device__ __forceinline__ void cp16(uint32_t s, const void* g) {
    asm volatile("cp.async.cg.shared.global [%0], [%1], 16;" :: "r"(s), "l"(g));
}
#define CP_COMMIT() asm volatile("cp.async.commit_group;" ::: "memory")
#define CP_WAIT3()  asm volatile("cp.async.wait_group 3;" ::: "memory")
#define CP_WAIT2()  asm volatile("cp.async.wait_group 2;" ::: "memory")
#define CP_WAIT1()  asm volatile("cp.async.wait_group 1;" ::: "memory")
#define CP_WAIT0()  asm volatile("cp.async.wait_group 0;" ::: "memory")
__device__ __forceinline__ void ldsm4(uint32_t* r, uint32_t addr) {
    asm volatile("ldmatrix.sync.aligned.m8n8.x4.shared.b16 {%0,%1,%2,%3}, [%4];"
                 : "=r"(r[0]), "=r"(r[1]), "=r"(r[2]), "=r"(r[3]) : "r"(addr));
}
__device__ __forceinline__ void mma16816(float* c, const uint32_t* a, uint32_t b0, uint32_t b1) {
    asm volatile("mma.sync.aligned.m16n8k16.row.col.f32.f16.f16.f32 "
        "{%0,%1,%2,%3},{%4,%5,%6,%7},{%8,%9},{%0,%1,%2,%3};"
        : "+f"(c[0]), "+f"(c[1]), "+f"(c[2]), "+f"(c[3])
        : "r"(a[0]), "r"(a[1]), "r"(a[2]), "r"(a[3]), "r"(b0), "r"(b1));
}
__device__ __forceinline__ uint2 pk4(float4 v) {
    __half2 h0 = __floats2half2_rn(v.x, v.y), h1 = __floats2half2_rn(v.z, v.w);
    return make_uint2(*reinterpret_cast<uint32_t*>(&h0), *reinterpret_cast<uint32_t*>(&h1));
}
__device__ __forceinline__ float swiglu(float g, float u) {
    g = fminf(g, 10.0f);
    u = fminf(fmaxf(u, -10.0f), 10.0f);
    return (g / (1.0f + __expf(-g))) * u;
}
__device__ __forceinline__ uint32_t swz(int row, int c) {
    return (uint32_t)(row * 64 + ((c ^ ((row >> 1) & 3)) << 4));
}

// ---------------- prep kernels ----------------
// fp32 -> fp16 weight conversion; block (0,0) also zeroes expert counters
__global__ void __launch_bounds__(256) convw(const float* __restrict__ GW,
                                             const float* __restrict__ UW,
                                             const float* __restrict__ DW) {
    if (blockIdx.x == 0 && blockIdx.y == 0 && threadIdx.x < N_EXP)
        g_cnt[threadIdx.x] = 0;
    const float* src = (blockIdx.y == 0) ? GW : (blockIdx.y == 1) ? UW : DW;
    __half* dst = (blockIdx.y == 0) ? g_gw16 : (blockIdx.y == 1) ? g_uw16 : g_dw16;
    size_t q = (size_t)blockIdx.x * 256 + threadIdx.x;
    float4 v = ((const float4*)src)[q];
    ((uint2*)dst)[q] = pk4(v);
}

// fused route + gather: one block per routed row
__global__ void __launch_bounds__(128) dispatch_kernel(const int* __restrict__ idx,
                                                       const float* __restrict__ H) {
    __shared__ int ss;
    const int r = blockIdx.x;
    if (threadIdx.x == 0) {
        int e = idx[r];
        int p = atomicAdd(&g_cnt[e], 1);
        int s = (p < CAP) ? (e * CAP + p) : -1;
        g_slot[r] = s;
        ss = s;
    }
    __syncthreads();
    const int s = ss;
    if (s < 0) return;
    const float4* src = (const float4*)(H + (size_t)(r >> 1) * K_DIM);
    uint2* dst = (uint2*)(g_x16 + (size_t)s * K_DIM);
#pragma unroll
    for (int i = 0; i < 4; i++) {
        int q = threadIdx.x + i * 128;
        dst[q] = pk4(src[q]);
    }
}

// ---------------- GEMMs (5-stage cp.async pipeline) ----------------
#define STAGE_B 16384
#define NSTAGE  5
extern __shared__ char smc[];

__device__ __forceinline__ void pipe_wait(int kt, int NT) {
    int rem = NT - 1 - kt;
    if (rem >= 3)      CP_WAIT3();
    else if (rem == 2) CP_WAIT2();
    else if (rem == 1) CP_WAIT1();
    else               CP_WAIT0();
}

// GEMM1: G = X@GW^T, U = X@UW^T (CTA 128m x 64n each), SwiGLU -> g_act
// stage: A(128rows)@0  G(64)@8192  U(64)@12288  (rows of 32 fp16)
__global__ void __launch_bounds__(256, 2) gemm1_tc() {
    const int e = blockIdx.z;
    int cnt = g_cnt[e]; if (cnt > CAP) cnt = CAP;
    const int m0 = blockIdx.x * 128;          // m fastest: consecutive CTAs share B
    if (m0 >= cnt) return;
    const int n0 = blockIdx.y * 64;

    const int tid = threadIdx.x, lane = tid & 31, wid = tid >> 5;
    const int wm = wid >> 2, wn = wid & 3;
    const int gq = lane >> 2, tg = lane & 3;
    const int lane15 = lane & 15, lhi = lane >> 4;

    const uint32_t su = smem_u32(smc);

    const int lrow = tid >> 2, lc = tid & 3;
    const __half* pa0 = g_x16 + ((size_t)(e * CAP + m0) + lrow) * K_DIM + lc * 8;
    const __half* pa1 = pa0 + (size_t)64 * K_DIM;
    const __half* pg  = g_gw16 + ((size_t)e * N_DIM + n0 + lrow) * K_DIM + lc * 8;
    const __half* pu  = g_uw16 + ((size_t)e * N_DIM + n0 + lrow) * K_DIM + lc * 8;
    const uint32_t soA0 = swz(lrow, lc), soA1 = swz(lrow + 64, lc);
    const uint32_t soG = 8192 + swz(lrow, lc), soU = 12288 + swz(lrow, lc);

    auto load = [&](int kt) {
        const uint32_t sb = su + (uint32_t)(kt % NSTAGE) * STAGE_B;
        const int ko = kt * 32;
        cp16(sb + soA0, pa0 + ko);
        cp16(sb + soA1, pa1 + ko);
        cp16(sb + soG,  pg  + ko);
        cp16(sb + soU,  pu  + ko);
        CP_COMMIT();
    };

    int aoff[4], axr[4];
#pragma unroll
    for (int i = 0; i < 4; i++) {
        int r = wm * 64 + i * 16 + lane15;
        aoff[i] = r * 64; axr[i] = (r >> 1) & 3;
    }
    const int brw = wn * 16 + lane15;
    const int boff = brw * 64, bxr = (brw >> 1) & 3;

    float cG[4][2][4] = {}, cU[4][2][4] = {};

    const int NT = K_DIM / 32;   // 64
    load(0); load(1); load(2); load(3);
    for (int kt = 0; kt < NT; ++kt) {
        pipe_wait(kt, NT);
        __syncthreads();
        if (kt + 4 < NT) load(kt + 4);

        const uint32_t sb = su + (uint32_t)(kt % NSTAGE) * STAGE_B;
#pragma unroll
        for (int kh = 0; kh < 2; ++kh) {
            const int ch = 2 * kh + lhi;
            uint32_t bg[4], bu[4];
            ldsm4(bg, sb + 8192  + boff + ((ch ^ bxr) << 4));
            ldsm4(bu, sb + 12288 + boff + ((ch ^ bxr) << 4));
#pragma unroll
            for (int i = 0; i < 4; i++) {
                uint32_t a[4];
                ldsm4(a, sb + aoff[i] + ((ch ^ axr[i]) << 4));
                mma16816(cG[i][0], a, bg[0], bg[2]);
                mma16816(cG[i][1], a, bg[1], bg[3]);
                mma16816(cU[i][0], a, bu[0], bu[2]);
                mma16816(cU[i][1], a, bu[1], bu[3]);
            }
        }
    }

#pragma unroll
    for (int i = 0; i < 4; i++) {
        int r0 = wm * 64 + i * 16 + gq;
        int mg0 = m0 + r0, mg1 = mg0 + 8;
        __half* row0 = g_act + ((size_t)e * CAP + mg0) * N_DIM + n0;
        __half* row1 = g_act + ((size_t)e * CAP + mg1) * N_DIM + n0;
#pragma unroll
        for (int j = 0; j < 2; j++) {
            int col = wn * 16 + j * 8 + tg * 2;
            if (mg0 < cnt)
                *(__half2*)(row0 + col) = __floats2half2_rn(
                    swiglu(cG[i][j][0], cU[i][j][0]), swiglu(cG[i][j][1], cU[i][j][1]));
            if (mg1 < cnt)
                *(__half2*)(row1 + col) = __floats2half2_rn(
                    swiglu(cG[i][j][2], cU[i][j][2]), swiglu(cG[i][j][3], cU[i][j][3]));
        }
    }
}

// GEMM2: D = act@DW^T (CTA 128m x 128n) -> g_stage (fp16, plain stores)
// stage: A(128rows)@0  B(128rows)@8192
__global__ void __launch_bounds__(256, 2) gemm2_tc() {
    const int e = blockIdx.z;
    int cnt = g_cnt[e]; if (cnt > CAP) cnt = CAP;
    const int m0 = blockIdx.x * 128;          // m fastest
    if (m0 >= cnt) return;
    const int n0 = blockIdx.y * 128;

    const int tid = threadIdx.x, lane = tid & 31, wid = tid >> 5;
    const int wm = wid >> 2, wn = wid & 3;
    const int gq = lane >> 2, tg = lane & 3;
    const int lane15 = lane & 15, lhi = lane >> 4;

    const uint32_t su = smem_u32(smc);

    const int lrow = tid >> 2, lc = tid & 3;
    const __half* pa0 = g_act + ((size_t)(e * CAP + m0) + lrow) * N_DIM + lc * 8;
    const __half* pa1 = pa0 + (size_t)64 * N_DIM;
    const __half* pb0 = g_dw16 + ((size_t)e * K_DIM + n0 + lrow) * N_DIM + lc * 8;
    const __half* pb1 = pb0 + (size_t)64 * N_DIM;
    const uint32_t soA0 = swz(lrow, lc), soA1 = swz(lrow + 64, lc);
    const uint32_t soB0 = 8192 + soA0, soB1 = 8192 + soA1;

    auto load = [&](int kt) {
        const uint32_t sb = su + (uint32_t)(kt % NSTAGE) * STAGE_B;
        const int ko = kt * 32;
        cp16(sb + soA0, pa0 + ko);
        cp16(sb + soA1, pa1 + ko);
        cp16(sb + soB0, pb0 + ko);
        cp16(sb + soB1, pb1 + ko);
        CP_COMMIT();
    };

    int aoff[4], axr[4];
#pragma unroll
    for (int i = 0; i < 4; i++) {
        int r = wm * 64 + i * 16 + lane15;
        aoff[i] = r * 64; axr[i] = (r >> 1) & 3;
    }
    int boff[2], bxr[2];
#pragma unroll
    for (int j = 0; j < 2; j++) {
        int r = wn * 32 + j * 16 + lane15;
        boff[j] = 8192 + r * 64; bxr[j] = (r >> 1) & 3;
    }

    float c[4][4][4] = {};

    const int NT = N_DIM / 32;   // 44
    load(0); load(1); load(2); load(3);
    for (int kt = 0; kt < NT; ++kt) {
        pipe_wait(kt, NT);
        __syncthreads();
        if (kt + 4 < NT) load(kt + 4);

        const uint32_t sb = su + (uint32_t)(kt % NSTAGE) * STAGE_B;
#pragma unroll
        for (int kh = 0; kh < 2; ++kh) {
            const int ch = 2 * kh + lhi;
            uint32_t b0[4], b1[4];
            ldsm4(b0, sb + boff[0] + ((ch ^ bxr[0]) << 4));
            ldsm4(b1, sb + boff[1] + ((ch ^ bxr[1]) << 4));
#pragma unroll
            for (int i = 0; i < 4; i++) {
                uint32_t a[4];
                ldsm4(a, sb + aoff[i] + ((ch ^ axr[i]) << 4));
                mma16816(c[i][0], a, b0[0], b0[2]);
                mma16816(c[i][1], a, b0[1], b0[3]);
                mma16816(c[i][2], a, b1[0], b1[2]);
                mma16816(c[i][3], a, b1[1], b1[3]);
            }
        }
    }

#pragma unroll
    for (int i = 0; i < 4; i++) {
        int r0 = wm * 64 + i * 16 + gq, r1 = r0 + 8;
        bool v0 = (m0 + r0) < cnt, v1 = (m0 + r1) < cnt;
        __half* o0 = g_stage + ((size_t)e * CAP + m0 + r0) * K_DIM + n0;
        __half* o1 = g_stage + ((size_t)e * CAP + m0 + r1) * K_DIM + n0;
#pragma unroll
        for (int j = 0; j < 4; j++) {
            int col = wn * 32 + j * 8 + tg * 2;
            if (v0) *(__half2*)(o0 + col) = __floats2half2_rn(c[i][j][0], c[i][j][1]);
            if (v1) *(__half2*)(o1 + col) = __floats2half2_rn(c[i][j][2], c[i][j][3]);
        }
    }
}

// combine: out[t] = gate0 * stage[slot0] + gate1 * stage[slot1]
__global__ void __launch_bounds__(256) combine_kernel(const float* __restrict__ gate,
                                                      float* __restrict__ out) {
    int gid = blockIdx.x * 256 + threadIdx.x;
    int t = gid >> 8;
    int c = (gid & 255) * 8;
    int s0 = g_slot[2 * t], s1 = g_slot[2 * t + 1];
    float g0 = gate[2 * t], g1 = gate[2 * t + 1];
    float acc[8] = {0, 0, 0, 0, 0, 0, 0, 0};
    if (s0 >= 0) {
        uint4 v = *(const uint4*)(g_stage + (size_t)s0 * K_DIM + c);
        const __half2* h = (const __half2*)&v;
#pragma unroll
        for (int q = 0; q < 4; q++) {
            float2 f = __half22float2(h[q]);
            acc[2 * q]     = g0 * f.x;
            acc[2 * q + 1] = g0 * f.y;
        }
    }
    if (s1 >= 0) {
        uint4 v = *(const uint4*)(g_stage + (size_t)s1 * K_DIM + c);
        const __half2* h = (const __half2*)&v;
#pragma unroll
        for (int q = 0; q < 4; q++) {
            float2 f = __half22float2(h[q]);
            acc[2 * q]     += g1 * f.x;
            acc[2 * q + 1] += g1 * f.y;
        }
    }
    float4* po = (float4*)(out + (size_t)t * K_DIM + c);
    po[0] = make_float4(acc[0], acc[1], acc[2], acc[3]);
    po[1] = make_float4(acc[4], acc[5], acc[6], acc[7]);
}

// ---------------------------------------------------------------------------
extern "C" void kernel_launch(void* const* d_in, const int* in_sizes, int n_in,
                              void* d_out, int out_size) {
    const float* H   = (const float*)d_in[0];
    const int*   IDX = (const int*)  d_in[1];
    const float* G   = (const float*)d_in[2];
    const float* GW  = (const float*)d_in[3];
    const float* UW  = (const float*)d_in[4];
    const float* DW  = (const float*)d_in[5];
    float* OUT = (float*)d_out;

    const int gsm = NSTAGE * STAGE_B;   // 80KB
    cudaFuncSetAttribute(gemm1_tc, cudaFuncAttributeMaxDynamicSharedMemorySize, gsm);
    cudaFuncSetAttribute(gemm2_tc, cudaFuncAttributeMaxDynamicSharedMemorySize, gsm);

    dim3 cw(W_ELEMS / 4 / 256, 3);
    convw<<<cw, 256>>>(GW, UW, DW);
    dispatch_kernel<<<N_ROWS, 128>>>(IDX, H);

    dim3 g1(CAP / 128, N_DIM / 64, N_EXP);         // 8 x 22 x 8
    gemm1_tc<<<g1, 256, gsm>>>();
    dim3 g2(CAP / 128, K_DIM / 128, N_EXP);        // 8 x 16 x 8
    gemm2_tc<<<g2, 256, gsm>>>();

    combine_kernel<<<M_TOK * K_DIM / 8 / 256, 256>>>(G, OUT);
}